// round 2
// baseline (speedup 1.0000x reference)
#include <cuda_runtime.h>
#include <math.h>

// ---------------------------------------------------------------------------
// Problem constants
// ---------------------------------------------------------------------------
#define IMG_H 1280
#define IMG_W 720
#define NH 64
#define NW 36
#define L_BLOCKS 2304           // 64*36
#define OUT_H 5120              // 1280*4
#define OUT_W 2880              // 720*4
#define OUT_PLANE (OUT_H * OUT_W)       // 14745600
#define OUT_IMG (3 * OUT_PLANE)          // 44236800

// gate intermediates
#define G1_C 16
#define G1_H 640
#define G1_W 360
#define G2_C 8
#define G2_H 320
#define G2_W 180

__device__ float g_g1[G1_C * G1_H * G1_W];   // 14.7 MB
__device__ float g_g2[G2_C * G2_H * G2_W];   // 1.8 MB

// ---------------------------------------------------------------------------
// Kernel D: light expert per 20x20 block -> clamp -> +0.4 -> pixel_shuffle(4)
// one CTA per block, 256 threads; float4 coalesced stores
// ---------------------------------------------------------------------------
__global__ __launch_bounds__(256, 8)
void light_kernel(const float* __restrict__ in,
                  const float* __restrict__ wl,
                  const float* __restrict__ bl,
                  float* __restrict__ out)
{
    __shared__ float s_in[3][22][22];     // zero-padded block
    __shared__ float s_w[48 * 27];
    __shared__ float s_b[48];

    const int tid = threadIdx.x;
    const int blk = blockIdx.x;
    const int bh = blk / NW;
    const int bw = blk % NW;

    for (int i = tid; i < 48 * 27; i += 256) s_w[i] = wl[i];
    if (tid < 48) s_b[tid] = bl[tid];

    for (int i = tid; i < 3 * 22 * 22; i += 256) {
        int x = i % 22;
        int y = (i / 22) % 22;
        int c = i / 484;
        float v = 0.0f;
        if (y >= 1 && y <= 20 && x >= 1 && x <= 20) {
            v = in[c * (IMG_H * IMG_W) + (bh * 20 + y - 1) * IMG_W + (bw * 20 + x - 1)];
        }
        s_in[c][y][x] = v;
    }
    __syncthreads();

    // work item = (c, r1, p, q): 3*4*20*20 = 4800
    for (int item = tid; item < 4800; item += 256) {
        int q  = item % 20;
        int p  = (item / 20) % 20;
        int r1 = (item / 400) % 4;
        int c  = item / 1600;
        int ob = c * 16 + r1 * 4;     // 4 consecutive conv channels

        float a0 = s_b[ob + 0];
        float a1 = s_b[ob + 1];
        float a2 = s_b[ob + 2];
        float a3 = s_b[ob + 3];

        const float* wbase = &s_w[ob * 27];
        #pragma unroll
        for (int ic = 0; ic < 3; ic++) {
            #pragma unroll
            for (int kh = 0; kh < 3; kh++) {
                #pragma unroll
                for (int kw = 0; kw < 3; kw++) {
                    float x = s_in[ic][p + kh][q + kw];
                    int wo = ic * 9 + kh * 3 + kw;
                    a0 = fmaf(x, wbase[wo +  0], a0);
                    a1 = fmaf(x, wbase[wo + 27], a1);
                    a2 = fmaf(x, wbase[wo + 54], a2);
                    a3 = fmaf(x, wbase[wo + 81], a3);
                }
            }
        }

        float4 v;
        v.x = fminf(fmaxf(a0, 0.0f), 0.6f) + 0.4f;
        v.y = fminf(fmaxf(a1, 0.0f), 0.6f) + 0.4f;
        v.z = fminf(fmaxf(a2, 0.0f), 0.6f) + 0.4f;
        v.w = fminf(fmaxf(a3, 0.0f), 0.6f) + 0.4f;

        int oy = bh * 80 + p * 4 + r1;
        int ox = bw * 80 + q * 4;
        *reinterpret_cast<float4*>(&out[(size_t)c * OUT_PLANE + (size_t)oy * OUT_W + ox]) = v;
    }
}

// ---------------------------------------------------------------------------
// Kernel A: gate conv1 (edge pad) + tanh + maxpool2 -> g1 [16,640,360]
// 16x16 pooled tile per CTA
// ---------------------------------------------------------------------------
__global__ __launch_bounds__(256, 4)
void gate1_kernel(const float* __restrict__ in,
                  const float* __restrict__ w1,
                  const float* __restrict__ b1)
{
    __shared__ float s_in[3][34][34];
    __shared__ float s_w[16 * 27];
    __shared__ float s_b[16];

    const int tx = threadIdx.x, ty = threadIdx.y;
    const int tid = ty * 16 + tx;
    const int ty0 = blockIdx.y * 16;
    const int tx0 = blockIdx.x * 16;

    // FIX (R2): 432 weights > 256 threads -> must be a strided loop
    for (int i = tid; i < 16 * 27; i += 256) s_w[i] = w1[i];
    if (tid < 16) s_b[tid] = b1[tid];

    for (int i = tid; i < 3 * 34 * 34; i += 256) {
        int x = i % 34;
        int y = (i / 34) % 34;
        int c = i / (34 * 34);
        int gy = min(max(ty0 * 2 - 1 + y, 0), IMG_H - 1);
        int gx = min(max(tx0 * 2 - 1 + x, 0), IMG_W - 1);
        s_in[c][y][x] = in[c * (IMG_H * IMG_W) + gy * IMG_W + gx];
    }
    __syncthreads();

    float m[16];
    #pragma unroll
    for (int o = 0; o < 16; o++) m[o] = -1e30f;

    #pragma unroll
    for (int dy = 0; dy < 2; dy++) {
        #pragma unroll
        for (int dx = 0; dx < 2; dx++) {
            float a[16];
            #pragma unroll
            for (int o = 0; o < 16; o++) a[o] = s_b[o];
            #pragma unroll
            for (int ic = 0; ic < 3; ic++) {
                #pragma unroll
                for (int kh = 0; kh < 3; kh++) {
                    #pragma unroll
                    for (int kw = 0; kw < 3; kw++) {
                        float x = s_in[ic][2 * ty + dy + kh][2 * tx + dx + kw];
                        int wo = ic * 9 + kh * 3 + kw;
                        #pragma unroll
                        for (int o = 0; o < 16; o++)
                            a[o] = fmaf(x, s_w[o * 27 + wo], a[o]);
                    }
                }
            }
            #pragma unroll
            for (int o = 0; o < 16; o++) m[o] = fmaxf(m[o], tanhf(a[o]));
        }
    }

    int py = ty0 + ty;
    int px = tx0 + tx;
    if (py < G1_H && px < G1_W) {
        #pragma unroll
        for (int o = 0; o < 16; o++)
            g_g1[o * (G1_H * G1_W) + py * G1_W + px] = m[o];
    }
}

// ---------------------------------------------------------------------------
// Kernel B: gate conv2 (edge pad) + maxpool2 -> g2 [8,320,180]
// 16x16 pooled tile per CTA, loop over 16 input channels
// ---------------------------------------------------------------------------
__global__ __launch_bounds__(256, 4)
void gate2_kernel(const float* __restrict__ w2,
                  const float* __restrict__ b2)
{
    __shared__ float s[34][34];
    __shared__ float s_w[8 * 16 * 9];

    const int tx = threadIdx.x, ty = threadIdx.y;
    const int tid = ty * 16 + tx;
    const int ty0 = blockIdx.y * 16;
    const int tx0 = blockIdx.x * 16;

    for (int i = tid; i < 8 * 16 * 9; i += 256) s_w[i] = w2[i];

    float acc[4][8];
    #pragma unroll
    for (int p = 0; p < 4; p++)
        #pragma unroll
        for (int o = 0; o < 8; o++) acc[p][o] = 0.0f;

    for (int ic = 0; ic < 16; ic++) {
        __syncthreads();
        for (int i = tid; i < 34 * 34; i += 256) {
            int x = i % 34;
            int y = i / 34;
            int gy = min(max(ty0 * 2 - 1 + y, 0), G1_H - 1);
            int gx = min(max(tx0 * 2 - 1 + x, 0), G1_W - 1);
            s[y][x] = g_g1[ic * (G1_H * G1_W) + gy * G1_W + gx];
        }
        __syncthreads();

        #pragma unroll
        for (int dy = 0; dy < 2; dy++) {
            #pragma unroll
            for (int dx = 0; dx < 2; dx++) {
                #pragma unroll
                for (int kh = 0; kh < 3; kh++) {
                    #pragma unroll
                    for (int kw = 0; kw < 3; kw++) {
                        float x = s[2 * ty + dy + kh][2 * tx + dx + kw];
                        int wo = ic * 9 + kh * 3 + kw;
                        #pragma unroll
                        for (int o = 0; o < 8; o++)
                            acc[dy * 2 + dx][o] = fmaf(x, s_w[o * (16 * 9) + wo], acc[dy * 2 + dx][o]);
                    }
                }
            }
        }
    }

    int py = ty0 + ty;
    int px = tx0 + tx;
    if (py < G2_H && px < G2_W) {
        #pragma unroll
        for (int o = 0; o < 8; o++) {
            float m = fmaxf(fmaxf(acc[0][o], acc[1][o]), fmaxf(acc[2][o], acc[3][o]));
            g_g2[o * (G2_H * G2_W) + py * G2_W + px] = m + b2[o];
        }
    }
}

// ---------------------------------------------------------------------------
// Kernel C: gate conv3 (5x5 stride 5) + sigmoid -> class_vector [2304]
// ---------------------------------------------------------------------------
__global__ __launch_bounds__(256)
void gate3_kernel(const float* __restrict__ w3,
                  const float* __restrict__ b3,
                  float* __restrict__ out_cv)
{
    __shared__ float s_w[200];
    int tid = threadIdx.x;
    if (tid < 200) s_w[tid] = w3[tid];
    __syncthreads();

    int idx = blockIdx.x * 256 + tid;
    if (idx >= L_BLOCKS) return;
    int by = idx / NW;
    int bx = idx % NW;

    float v = b3[0];
    #pragma unroll
    for (int ic = 0; ic < 8; ic++) {
        #pragma unroll
        for (int ky = 0; ky < 5; ky++) {
            #pragma unroll
            for (int kx = 0; kx < 5; kx++) {
                v = fmaf(g_g2[ic * (G2_H * G2_W) + (by * 5 + ky) * G2_W + (bx * 5 + kx)],
                         s_w[ic * 25 + ky * 5 + kx], v);
            }
        }
    }
    out_cv[idx] = 1.0f / (1.0f + expf(-v));
}

// ---------------------------------------------------------------------------
// Launch
// ---------------------------------------------------------------------------
extern "C" void kernel_launch(void* const* d_in, const int* in_sizes, int n_in,
                              void* d_out, int out_size)
{
    const float* in = (const float*)d_in[0];
    const float* w1 = (const float*)d_in[1];
    const float* b1 = (const float*)d_in[2];
    const float* w2 = (const float*)d_in[3];
    const float* b2 = (const float*)d_in[4];
    const float* w3 = (const float*)d_in[5];
    const float* b3 = (const float*)d_in[6];
    const float* wl = (const float*)d_in[7];
    const float* bl = (const float*)d_in[8];
    // d_in[9..14] = complex expert weights: provably dead (sigmoid > 1 is never true)

    float* out = (float*)d_out;

    // Light expert (independent of gate; dominates runtime)
    light_kernel<<<L_BLOCKS, 256>>>(in, wl, bl, out);

    // Gate CNN chain -> class_vector appended after the image
    dim3 bt(16, 16);
    gate1_kernel<<<dim3((G1_W + 15) / 16, (G1_H + 15) / 16), bt>>>(in, w1, b1);
    gate2_kernel<<<dim3((G2_W + 15) / 16, (G2_H + 15) / 16), bt>>>(w2, b2);
    gate3_kernel<<<(L_BLOCKS + 255) / 256, 256>>>(w3, b3, out + OUT_IMG);
}

// round 3
// speedup vs baseline: 1.5115x; 1.5115x over previous
#include <cuda_runtime.h>
#include <math.h>

typedef unsigned long long u64;

// ---------------------------------------------------------------------------
// Packed f32x2 helpers (Blackwell FFMA2 — only reachable via PTX fma.rn.f32x2)
// ---------------------------------------------------------------------------
__device__ __forceinline__ u64 pack2(float x) {
    u64 r; asm("mov.b64 %0, {%1, %1};" : "=l"(r) : "f"(x)); return r;
}
__device__ __forceinline__ void unpack2(u64 v, float& lo, float& hi) {
    asm("mov.b64 {%0, %1}, %2;" : "=f"(lo), "=f"(hi) : "l"(v));
}
__device__ __forceinline__ u64 fma2(u64 a, u64 b, u64 c) {
    u64 d; asm("fma.rn.f32x2 %0, %1, %2, %3;" : "=l"(d) : "l"(a), "l"(b), "l"(c));
    return d;
}

// ---------------------------------------------------------------------------
// Problem constants
// ---------------------------------------------------------------------------
#define IMG_H 1280
#define IMG_W 720
#define NH 64
#define NW 36
#define L_BLOCKS 2304
#define OUT_H 5120
#define OUT_W 2880
#define OUT_PLANE (OUT_H * OUT_W)
#define OUT_IMG (3 * OUT_PLANE)

#define G1_C 16
#define G1_H 640
#define G1_W 360
#define G1_AREA (G1_H * G1_W)
#define G2_C 8
#define G2_H 320
#define G2_W 180
#define G2_AREA (G2_H * G2_W)

__device__ float g_g1[G1_C * G1_AREA];
__device__ float g_g2[G2_C * G2_AREA];

// ---------------------------------------------------------------------------
// Kernel D: light expert. One CTA per 20x20 block.
// Thread = 8 conv channels (4 f32x2 pairs) x 2x5 pixel patch.
// Weights transposed in smem -> broadcast LDS.64 pair loads.
// ---------------------------------------------------------------------------
__global__ __launch_bounds__(256)
void light_kernel(const float* __restrict__ in,
                  const float* __restrict__ wl,
                  const float* __restrict__ bl,
                  float* __restrict__ out)
{
    __shared__ float s_in[3][22][22];
    __shared__ float s_wT[27][48];     // [k-position][out channel]
    __shared__ float s_b[48];

    const int tid = threadIdx.x;
    const int blk = blockIdx.x;
    const int bh = blk / NW;
    const int bw = blk % NW;

    for (int i = tid; i < 27 * 48; i += 256) {
        int k = i / 48, oc = i % 48;
        s_wT[k][oc] = wl[oc * 27 + k];
    }
    if (tid < 48) s_b[tid] = bl[tid];

    for (int i = tid; i < 3 * 22 * 22; i += 256) {
        int x = i % 22;
        int y = (i / 22) % 22;
        int c = i / 484;
        float v = 0.0f;
        if (y >= 1 && y <= 20 && x >= 1 && x <= 20)
            v = in[c * (IMG_H * IMG_W) + (bh * 20 + y - 1) * IMG_W + (bw * 20 + x - 1)];
        s_in[c][y][x] = v;
    }
    __syncthreads();

    if (tid < 240) {
        const int cg = tid / 40;          // channel group: oc0 = cg*8
        const int patch = tid % 40;       // pp(0..9) x qq(0..3)
        const int p0 = (patch >> 2) * 2;  // 2 rows
        const int q0 = (patch & 3) * 5;   // 5 cols
        const int oc0 = cg * 8;

        u64 acc[2][5][4];
        {
            u64 b0 = *(const u64*)&s_b[oc0 + 0];
            u64 b1 = *(const u64*)&s_b[oc0 + 2];
            u64 b2 = *(const u64*)&s_b[oc0 + 4];
            u64 b3 = *(const u64*)&s_b[oc0 + 6];
            #pragma unroll
            for (int r = 0; r < 2; r++)
                #pragma unroll
                for (int j = 0; j < 5; j++) {
                    acc[r][j][0] = b0; acc[r][j][1] = b1;
                    acc[r][j][2] = b2; acc[r][j][3] = b3;
                }
        }

        #pragma unroll
        for (int ic = 0; ic < 3; ic++) {
            #pragma unroll
            for (int kh = 0; kh < 3; kh++) {
                u64 xx[2][7];
                #pragma unroll
                for (int r = 0; r < 2; r++)
                    #pragma unroll
                    for (int c = 0; c < 7; c++)
                        xx[r][c] = pack2(s_in[ic][p0 + kh + r][q0 + c]);
                #pragma unroll
                for (int kw = 0; kw < 3; kw++) {
                    const float* wp = &s_wT[ic * 9 + kh * 3 + kw][oc0];
                    u64 w0 = *(const u64*)(wp + 0);
                    u64 w1 = *(const u64*)(wp + 2);
                    u64 w2 = *(const u64*)(wp + 4);
                    u64 w3 = *(const u64*)(wp + 6);
                    #pragma unroll
                    for (int r = 0; r < 2; r++)
                        #pragma unroll
                        for (int j = 0; j < 5; j++) {
                            u64 x = xx[r][j + kw];
                            acc[r][j][0] = fma2(x, w0, acc[r][j][0]);
                            acc[r][j][1] = fma2(x, w1, acc[r][j][1]);
                            acc[r][j][2] = fma2(x, w2, acc[r][j][2]);
                            acc[r][j][3] = fma2(x, w3, acc[r][j][3]);
                        }
                }
            }
        }

        // Store: quad A = oc0..oc0+3 (r1a), quad B = oc0+4..oc0+7 (r1a+1)
        const int c_img = oc0 >> 4;
        const int r1a = (oc0 & 15) >> 2;
        #pragma unroll
        for (int r = 0; r < 2; r++)
            #pragma unroll
            for (int j = 0; j < 5; j++) {
                int p = p0 + r, q = q0 + j;
                size_t base = (size_t)c_img * OUT_PLANE
                            + (size_t)(bh * 80 + p * 4 + r1a) * OUT_W
                            + (bw * 80 + q * 4);
                float4 v;
                unpack2(acc[r][j][0], v.x, v.y);
                unpack2(acc[r][j][1], v.z, v.w);
                v.x = fminf(fmaxf(v.x, 0.0f), 0.6f) + 0.4f;
                v.y = fminf(fmaxf(v.y, 0.0f), 0.6f) + 0.4f;
                v.z = fminf(fmaxf(v.z, 0.0f), 0.6f) + 0.4f;
                v.w = fminf(fmaxf(v.w, 0.0f), 0.6f) + 0.4f;
                *reinterpret_cast<float4*>(&out[base]) = v;

                unpack2(acc[r][j][2], v.x, v.y);
                unpack2(acc[r][j][3], v.z, v.w);
                v.x = fminf(fmaxf(v.x, 0.0f), 0.6f) + 0.4f;
                v.y = fminf(fmaxf(v.y, 0.0f), 0.6f) + 0.4f;
                v.z = fminf(fmaxf(v.z, 0.0f), 0.6f) + 0.4f;
                v.w = fminf(fmaxf(v.w, 0.0f), 0.6f) + 0.4f;
                *reinterpret_cast<float4*>(&out[base + OUT_W]) = v;
            }
    }
}

// ---------------------------------------------------------------------------
// Kernel A: gate conv1 + maxpool2 + tanh (swapped: tanh monotone) -> g1
// Thread = 16 channels (8 pairs) x 2x2 pool window. Weights transposed.
// ---------------------------------------------------------------------------
__global__ __launch_bounds__(256)
void gate1_kernel(const float* __restrict__ in,
                  const float* __restrict__ w1,
                  const float* __restrict__ b1)
{
    __shared__ float s_in[3][34][34];
    __shared__ float s_wT[27][16];
    __shared__ float s_b[16];

    const int tid = threadIdx.x;
    const int tx = tid & 15, ty = tid >> 4;
    const int ty0 = blockIdx.y * 16;
    const int tx0 = blockIdx.x * 16;

    for (int i = tid; i < 27 * 16; i += 256) {
        int k = i >> 4, oc = i & 15;
        s_wT[k][oc] = w1[oc * 27 + k];
    }
    if (tid < 16) s_b[tid] = b1[tid];

    for (int i = tid; i < 3 * 34 * 34; i += 256) {
        int x = i % 34;
        int y = (i / 34) % 34;
        int c = i / 1156;
        int gy = min(max(ty0 * 2 - 1 + y, 0), IMG_H - 1);
        int gx = min(max(tx0 * 2 - 1 + x, 0), IMG_W - 1);
        s_in[c][y][x] = in[c * (IMG_H * IMG_W) + gy * IMG_W + gx];
    }
    __syncthreads();

    u64 acc[2][2][8];
    {
        #pragma unroll
        for (int m = 0; m < 8; m++) {
            u64 b = *(const u64*)&s_b[2 * m];
            acc[0][0][m] = b; acc[0][1][m] = b;
            acc[1][0][m] = b; acc[1][1][m] = b;
        }
    }

    #pragma unroll
    for (int ic = 0; ic < 3; ic++) {
        #pragma unroll
        for (int kh = 0; kh < 3; kh++) {
            u64 xx[2][4];
            #pragma unroll
            for (int dy = 0; dy < 2; dy++)
                #pragma unroll
                for (int c = 0; c < 4; c++)
                    xx[dy][c] = pack2(s_in[ic][2 * ty + kh + dy][2 * tx + c]);
            #pragma unroll
            for (int kw = 0; kw < 3; kw++) {
                const float* wp = &s_wT[ic * 9 + kh * 3 + kw][0];
                u64 w[8];
                #pragma unroll
                for (int m = 0; m < 8; m++) w[m] = *(const u64*)(wp + 2 * m);
                #pragma unroll
                for (int dy = 0; dy < 2; dy++)
                    #pragma unroll
                    for (int dx = 0; dx < 2; dx++) {
                        u64 x = xx[dy][dx + kw];
                        #pragma unroll
                        for (int m = 0; m < 8; m++)
                            acc[dy][dx][m] = fma2(x, w[m], acc[dy][dx][m]);
                    }
            }
        }
    }

    int py = ty0 + ty;
    int px = tx0 + tx;
    if (py < G1_H && px < G1_W) {
        #pragma unroll
        for (int m = 0; m < 8; m++) {
            float m0 = -1e30f, m1 = -1e30f;
            #pragma unroll
            for (int dy = 0; dy < 2; dy++)
                #pragma unroll
                for (int dx = 0; dx < 2; dx++) {
                    float lo, hi;
                    unpack2(acc[dy][dx][m], lo, hi);
                    m0 = fmaxf(m0, lo);
                    m1 = fmaxf(m1, hi);
                }
            g_g1[(2 * m + 0) * G1_AREA + py * G1_W + px] = tanhf(m0);
            g_g1[(2 * m + 1) * G1_AREA + py * G1_W + px] = tanhf(m1);
        }
    }
}

// ---------------------------------------------------------------------------
// Kernel B: gate conv2 + maxpool2 -> g2. Two phases of 8 input channels
// staged in smem (2 syncs). Thread = 8 ch (4 pairs) x 2x2 pool window.
// ---------------------------------------------------------------------------
__global__ __launch_bounds__(256)
void gate2_kernel(const float* __restrict__ w2,
                  const float* __restrict__ b2)
{
    __shared__ float s_g[8][34][34];   // 37 KB
    __shared__ float s_wT[144][8];     // [ic*9+kh*3+kw][oc]

    const int tid = threadIdx.x;
    const int tx = tid & 15, ty = tid >> 4;
    const int ty0 = blockIdx.y * 16;
    const int tx0 = blockIdx.x * 16;

    for (int i = tid; i < 144 * 8; i += 256) {
        int k = i >> 3, oc = i & 7;
        s_wT[k][oc] = w2[oc * 144 + k];
    }

    u64 acc[2][2][4];
    u64 z = pack2(0.0f);
    #pragma unroll
    for (int dy = 0; dy < 2; dy++)
        #pragma unroll
        for (int dx = 0; dx < 2; dx++)
            #pragma unroll
            for (int m = 0; m < 4; m++) acc[dy][dx][m] = z;

    for (int half = 0; half < 2; half++) {
        __syncthreads();
        for (int i = tid; i < 8 * 34 * 34; i += 256) {
            int x = i % 34;
            int y = (i / 34) % 34;
            int c = i / 1156;
            int gy = min(max(ty0 * 2 - 1 + y, 0), G1_H - 1);
            int gx = min(max(tx0 * 2 - 1 + x, 0), G1_W - 1);
            s_g[c][y][x] = g_g1[(half * 8 + c) * G1_AREA + gy * G1_W + gx];
        }
        __syncthreads();

        #pragma unroll
        for (int ci = 0; ci < 8; ci++) {
            int ic = half * 8 + ci;
            #pragma unroll
            for (int kh = 0; kh < 3; kh++) {
                u64 xx[2][4];
                #pragma unroll
                for (int dy = 0; dy < 2; dy++)
                    #pragma unroll
                    for (int c = 0; c < 4; c++)
                        xx[dy][c] = pack2(s_g[ci][2 * ty + kh + dy][2 * tx + c]);
                #pragma unroll
                for (int kw = 0; kw < 3; kw++) {
                    const float* wp = &s_wT[ic * 9 + kh * 3 + kw][0];
                    u64 w0 = *(const u64*)(wp + 0);
                    u64 w1 = *(const u64*)(wp + 2);
                    u64 w2p = *(const u64*)(wp + 4);
                    u64 w3 = *(const u64*)(wp + 6);
                    #pragma unroll
                    for (int dy = 0; dy < 2; dy++)
                        #pragma unroll
                        for (int dx = 0; dx < 2; dx++) {
                            u64 x = xx[dy][dx + kw];
                            acc[dy][dx][0] = fma2(x, w0, acc[dy][dx][0]);
                            acc[dy][dx][1] = fma2(x, w1, acc[dy][dx][1]);
                            acc[dy][dx][2] = fma2(x, w2p, acc[dy][dx][2]);
                            acc[dy][dx][3] = fma2(x, w3, acc[dy][dx][3]);
                        }
                }
            }
        }
    }

    int py = ty0 + ty;
    int px = tx0 + tx;
    if (py < G2_H && px < G2_W) {
        #pragma unroll
        for (int m = 0; m < 4; m++) {
            float m0 = -1e30f, m1 = -1e30f;
            #pragma unroll
            for (int dy = 0; dy < 2; dy++)
                #pragma unroll
                for (int dx = 0; dx < 2; dx++) {
                    float lo, hi;
                    unpack2(acc[dy][dx][m], lo, hi);
                    m0 = fmaxf(m0, lo);
                    m1 = fmaxf(m1, hi);
                }
            g_g2[(2 * m + 0) * G2_AREA + py * G2_W + px] = m0 + b2[2 * m + 0];
            g_g2[(2 * m + 1) * G2_AREA + py * G2_W + px] = m1 + b2[2 * m + 1];
        }
    }
}

// ---------------------------------------------------------------------------
// Kernel C: gate conv3 (5x5 stride 5) + sigmoid. 8 lanes per output
// (one per input channel) + shuffle reduce.
// ---------------------------------------------------------------------------
__global__ __launch_bounds__(256)
void gate3_kernel(const float* __restrict__ w3,
                  const float* __restrict__ b3,
                  float* __restrict__ out_cv)
{
    __shared__ float s_w[200];
    int tid = threadIdx.x;
    if (tid < 200) s_w[tid] = w3[tid];
    __syncthreads();

    int lane = tid & 7;
    int o = blockIdx.x * 32 + (tid >> 3);
    if (o >= L_BLOCKS) return;
    int by = o / NW;
    int bx = o % NW;

    const float* gp = &g_g2[lane * G2_AREA + (by * 5) * G2_W + bx * 5];
    const float* wp = &s_w[lane * 25];

    float v = 0.0f;
    #pragma unroll
    for (int ky = 0; ky < 5; ky++)
        #pragma unroll
        for (int kx = 0; kx < 5; kx++)
            v = fmaf(gp[ky * G2_W + kx], wp[ky * 5 + kx], v);

    v += __shfl_xor_sync(0xffffffffu, v, 4);
    v += __shfl_xor_sync(0xffffffffu, v, 2);
    v += __shfl_xor_sync(0xffffffffu, v, 1);

    if (lane == 0)
        out_cv[o] = 1.0f / (1.0f + expf(-(v + b3[0])));
}

// ---------------------------------------------------------------------------
// Launch
// ---------------------------------------------------------------------------
extern "C" void kernel_launch(void* const* d_in, const int* in_sizes, int n_in,
                              void* d_out, int out_size)
{
    const float* in = (const float*)d_in[0];
    const float* w1 = (const float*)d_in[1];
    const float* b1 = (const float*)d_in[2];
    const float* w2 = (const float*)d_in[3];
    const float* b2 = (const float*)d_in[4];
    const float* w3 = (const float*)d_in[5];
    const float* b3 = (const float*)d_in[6];
    const float* wl = (const float*)d_in[7];
    const float* bl = (const float*)d_in[8];
    // complex expert weights (d_in[9..14]) are provably dead: sigmoid(x) > 1 never

    float* out = (float*)d_out;

    light_kernel<<<L_BLOCKS, 256>>>(in, wl, bl, out);

    dim3 bt(256);
    gate1_kernel<<<dim3((G1_W + 15) / 16, (G1_H + 15) / 16), bt>>>(in, w1, b1);
    gate2_kernel<<<dim3((G2_W + 15) / 16, (G2_H + 15) / 16), bt>>>(w2, b2);
    gate3_kernel<<<(L_BLOCKS + 31) / 32, 256>>>(w3, b3, out + OUT_IMG);
}

// round 4
// speedup vs baseline: 1.5515x; 1.0265x over previous
#include <cuda_runtime.h>
#include <math.h>

typedef unsigned long long u64;

// ---------------------------------------------------------------------------
// Packed f32x2 helpers (Blackwell FFMA2 — only reachable via PTX fma.rn.f32x2)
// ---------------------------------------------------------------------------
__device__ __forceinline__ u64 pack2(float x) {
    u64 r; asm("mov.b64 %0, {%1, %1};" : "=l"(r) : "f"(x)); return r;
}
__device__ __forceinline__ void unpack2(u64 v, float& lo, float& hi) {
    asm("mov.b64 {%0, %1}, %2;" : "=f"(lo), "=f"(hi) : "l"(v));
}
__device__ __forceinline__ u64 fma2(u64 a, u64 b, u64 c) {
    u64 d; asm("fma.rn.f32x2 %0, %1, %2, %3;" : "=l"(d) : "l"(a), "l"(b), "l"(c));
    return d;
}

// ---------------------------------------------------------------------------
// Problem constants
// ---------------------------------------------------------------------------
#define IMG_H 1280
#define IMG_W 720
#define NH 64
#define NW 36
#define L_BLOCKS 2304
#define OUT_H 5120
#define OUT_W 2880
#define OUT_PLANE (OUT_H * OUT_W)
#define OUT_IMG (3 * OUT_PLANE)

#define G1_C 16
#define G1_H 640
#define G1_W 360
#define G1_AREA (G1_H * G1_W)
#define G2_C 8
#define G2_H 320
#define G2_W 180
#define G2_AREA (G2_H * G2_W)

__device__ float g_g1[G1_C * G1_AREA];
__device__ float g_g2[G2_C * G2_AREA];

// ---------------------------------------------------------------------------
// Kernel D: light expert. One CTA per 20x20 block.
// Thread item = 8 conv channels (4 f32x2 pairs) x 1x5 pixels; 2 items/thread.
// Peak live state ~31 u64 -> ~80 regs -> 3 CTAs/SM.
// ---------------------------------------------------------------------------
__global__ __launch_bounds__(256)
void light_kernel(const float* __restrict__ in,
                  const float* __restrict__ wl,
                  const float* __restrict__ bl,
                  float* __restrict__ out)
{
    __shared__ float s_in[3][22][22];
    __shared__ float s_wT[27][48];     // [k-position][out channel]
    __shared__ float s_b[48];

    const int tid = threadIdx.x;
    const int blk = blockIdx.x;
    const int bh = blk / NW;
    const int bw = blk % NW;

    for (int i = tid; i < 27 * 48; i += 256) {
        int k = i / 48, oc = i % 48;
        s_wT[k][oc] = wl[oc * 27 + k];
    }
    if (tid < 48) s_b[tid] = bl[tid];

    for (int i = tid; i < 3 * 22 * 22; i += 256) {
        int x = i % 22;
        int y = (i / 22) % 22;
        int c = i / 484;
        float v = 0.0f;
        if (y >= 1 && y <= 20 && x >= 1 && x <= 20)
            v = in[c * (IMG_H * IMG_W) + (bh * 20 + y - 1) * IMG_W + (bw * 20 + x - 1)];
        s_in[c][y][x] = v;
    }
    __syncthreads();

    if (tid < 240) {
        #pragma unroll 1
        for (int it = 0; it < 2; it++) {
            const int item = tid + 240 * it;        // 0..479
            const int cg  = item / 80;              // 6 channel groups of 8
            const int rem = item % 80;
            const int p   = rem >> 2;               // row 0..19
            const int q0  = (rem & 3) * 5;          // col group 0..3 -> 5 cols
            const int oc0 = cg * 8;

            u64 acc[5][4];
            {
                u64 b0 = *(const u64*)&s_b[oc0 + 0];
                u64 b1 = *(const u64*)&s_b[oc0 + 2];
                u64 b2 = *(const u64*)&s_b[oc0 + 4];
                u64 b3 = *(const u64*)&s_b[oc0 + 6];
                #pragma unroll
                for (int j = 0; j < 5; j++) {
                    acc[j][0] = b0; acc[j][1] = b1;
                    acc[j][2] = b2; acc[j][3] = b3;
                }
            }

            #pragma unroll
            for (int ic = 0; ic < 3; ic++) {
                #pragma unroll
                for (int kh = 0; kh < 3; kh++) {
                    u64 xx[7];
                    #pragma unroll
                    for (int c = 0; c < 7; c++)
                        xx[c] = pack2(s_in[ic][p + kh][q0 + c]);
                    #pragma unroll
                    for (int kw = 0; kw < 3; kw++) {
                        const float* wp = &s_wT[ic * 9 + kh * 3 + kw][oc0];
                        u64 w0 = *(const u64*)(wp + 0);
                        u64 w1 = *(const u64*)(wp + 2);
                        u64 w2 = *(const u64*)(wp + 4);
                        u64 w3 = *(const u64*)(wp + 6);
                        #pragma unroll
                        for (int j = 0; j < 5; j++) {
                            u64 x = xx[j + kw];
                            acc[j][0] = fma2(x, w0, acc[j][0]);
                            acc[j][1] = fma2(x, w1, acc[j][1]);
                            acc[j][2] = fma2(x, w2, acc[j][2]);
                            acc[j][3] = fma2(x, w3, acc[j][3]);
                        }
                    }
                }
            }

            const int c_img = oc0 >> 4;
            const int r1a = (oc0 & 15) >> 2;
            #pragma unroll
            for (int j = 0; j < 5; j++) {
                int q = q0 + j;
                size_t base = (size_t)c_img * OUT_PLANE
                            + (size_t)(bh * 80 + p * 4 + r1a) * OUT_W
                            + (bw * 80 + q * 4);
                float4 v;
                unpack2(acc[j][0], v.x, v.y);
                unpack2(acc[j][1], v.z, v.w);
                v.x = fminf(fmaxf(v.x, 0.0f), 0.6f) + 0.4f;
                v.y = fminf(fmaxf(v.y, 0.0f), 0.6f) + 0.4f;
                v.z = fminf(fmaxf(v.z, 0.0f), 0.6f) + 0.4f;
                v.w = fminf(fmaxf(v.w, 0.0f), 0.6f) + 0.4f;
                *reinterpret_cast<float4*>(&out[base]) = v;

                unpack2(acc[j][2], v.x, v.y);
                unpack2(acc[j][3], v.z, v.w);
                v.x = fminf(fmaxf(v.x, 0.0f), 0.6f) + 0.4f;
                v.y = fminf(fmaxf(v.y, 0.0f), 0.6f) + 0.4f;
                v.z = fminf(fmaxf(v.z, 0.0f), 0.6f) + 0.4f;
                v.w = fminf(fmaxf(v.w, 0.0f), 0.6f) + 0.4f;
                *reinterpret_cast<float4*>(&out[base + OUT_W]) = v;
            }
        }
    }
}

// ---------------------------------------------------------------------------
// Kernel A: gate conv1 + maxpool2 + tanh (swapped: tanh monotone) -> g1
// ---------------------------------------------------------------------------
__global__ __launch_bounds__(256)
void gate1_kernel(const float* __restrict__ in,
                  const float* __restrict__ w1,
                  const float* __restrict__ b1)
{
    __shared__ float s_in[3][34][34];
    __shared__ float s_wT[27][16];
    __shared__ float s_b[16];

    const int tid = threadIdx.x;
    const int tx = tid & 15, ty = tid >> 4;
    const int ty0 = blockIdx.y * 16;
    const int tx0 = blockIdx.x * 16;

    for (int i = tid; i < 27 * 16; i += 256) {
        int k = i >> 4, oc = i & 15;
        s_wT[k][oc] = w1[oc * 27 + k];
    }
    if (tid < 16) s_b[tid] = b1[tid];

    for (int i = tid; i < 3 * 34 * 34; i += 256) {
        int x = i % 34;
        int y = (i / 34) % 34;
        int c = i / 1156;
        int gy = min(max(ty0 * 2 - 1 + y, 0), IMG_H - 1);
        int gx = min(max(tx0 * 2 - 1 + x, 0), IMG_W - 1);
        s_in[c][y][x] = in[c * (IMG_H * IMG_W) + gy * IMG_W + gx];
    }
    __syncthreads();

    u64 acc[2][2][8];
    {
        #pragma unroll
        for (int m = 0; m < 8; m++) {
            u64 b = *(const u64*)&s_b[2 * m];
            acc[0][0][m] = b; acc[0][1][m] = b;
            acc[1][0][m] = b; acc[1][1][m] = b;
        }
    }

    #pragma unroll
    for (int ic = 0; ic < 3; ic++) {
        #pragma unroll
        for (int kh = 0; kh < 3; kh++) {
            u64 xx[2][4];
            #pragma unroll
            for (int dy = 0; dy < 2; dy++)
                #pragma unroll
                for (int c = 0; c < 4; c++)
                    xx[dy][c] = pack2(s_in[ic][2 * ty + kh + dy][2 * tx + c]);
            #pragma unroll
            for (int kw = 0; kw < 3; kw++) {
                const float* wp = &s_wT[ic * 9 + kh * 3 + kw][0];
                u64 w[8];
                #pragma unroll
                for (int m = 0; m < 8; m++) w[m] = *(const u64*)(wp + 2 * m);
                #pragma unroll
                for (int dy = 0; dy < 2; dy++)
                    #pragma unroll
                    for (int dx = 0; dx < 2; dx++) {
                        u64 x = xx[dy][dx + kw];
                        #pragma unroll
                        for (int m = 0; m < 8; m++)
                            acc[dy][dx][m] = fma2(x, w[m], acc[dy][dx][m]);
                    }
            }
        }
    }

    int py = ty0 + ty;
    int px = tx0 + tx;
    if (py < G1_H && px < G1_W) {
        #pragma unroll
        for (int m = 0; m < 8; m++) {
            float m0 = -1e30f, m1 = -1e30f;
            #pragma unroll
            for (int dy = 0; dy < 2; dy++)
                #pragma unroll
                for (int dx = 0; dx < 2; dx++) {
                    float lo, hi;
                    unpack2(acc[dy][dx][m], lo, hi);
                    m0 = fmaxf(m0, lo);
                    m1 = fmaxf(m1, hi);
                }
            g_g1[(2 * m + 0) * G1_AREA + py * G1_W + px] = tanhf(m0);
            g_g1[(2 * m + 1) * G1_AREA + py * G1_W + px] = tanhf(m1);
        }
    }
}

// ---------------------------------------------------------------------------
// Kernel B: gate conv2 + maxpool2 -> g2
// ---------------------------------------------------------------------------
__global__ __launch_bounds__(256)
void gate2_kernel(const float* __restrict__ w2,
                  const float* __restrict__ b2)
{
    __shared__ float s_g[8][34][34];
    __shared__ float s_wT[144][8];

    const int tid = threadIdx.x;
    const int tx = tid & 15, ty = tid >> 4;
    const int ty0 = blockIdx.y * 16;
    const int tx0 = blockIdx.x * 16;

    for (int i = tid; i < 144 * 8; i += 256) {
        int k = i >> 3, oc = i & 7;
        s_wT[k][oc] = w2[oc * 144 + k];
    }

    u64 acc[2][2][4];
    u64 z = pack2(0.0f);
    #pragma unroll
    for (int dy = 0; dy < 2; dy++)
        #pragma unroll
        for (int dx = 0; dx < 2; dx++)
            #pragma unroll
            for (int m = 0; m < 4; m++) acc[dy][dx][m] = z;

    for (int half = 0; half < 2; half++) {
        __syncthreads();
        for (int i = tid; i < 8 * 34 * 34; i += 256) {
            int x = i % 34;
            int y = (i / 34) % 34;
            int c = i / 1156;
            int gy = min(max(ty0 * 2 - 1 + y, 0), G1_H - 1);
            int gx = min(max(tx0 * 2 - 1 + x, 0), G1_W - 1);
            s_g[c][y][x] = g_g1[(half * 8 + c) * G1_AREA + gy * G1_W + gx];
        }
        __syncthreads();

        #pragma unroll
        for (int ci = 0; ci < 8; ci++) {
            int ic = half * 8 + ci;
            #pragma unroll
            for (int kh = 0; kh < 3; kh++) {
                u64 xx[2][4];
                #pragma unroll
                for (int dy = 0; dy < 2; dy++)
                    #pragma unroll
                    for (int c = 0; c < 4; c++)
                        xx[dy][c] = pack2(s_g[ci][2 * ty + kh + dy][2 * tx + c]);
                #pragma unroll
                for (int kw = 0; kw < 3; kw++) {
                    const float* wp = &s_wT[ic * 9 + kh * 3 + kw][0];
                    u64 w0 = *(const u64*)(wp + 0);
                    u64 w1 = *(const u64*)(wp + 2);
                    u64 w2p = *(const u64*)(wp + 4);
                    u64 w3 = *(const u64*)(wp + 6);
                    #pragma unroll
                    for (int dy = 0; dy < 2; dy++)
                        #pragma unroll
                        for (int dx = 0; dx < 2; dx++) {
                            u64 x = xx[dy][dx + kw];
                            acc[dy][dx][0] = fma2(x, w0, acc[dy][dx][0]);
                            acc[dy][dx][1] = fma2(x, w1, acc[dy][dx][1]);
                            acc[dy][dx][2] = fma2(x, w2p, acc[dy][dx][2]);
                            acc[dy][dx][3] = fma2(x, w3, acc[dy][dx][3]);
                        }
                }
            }
        }
    }

    int py = ty0 + ty;
    int px = tx0 + tx;
    if (py < G2_H && px < G2_W) {
        #pragma unroll
        for (int m = 0; m < 4; m++) {
            float m0 = -1e30f, m1 = -1e30f;
            #pragma unroll
            for (int dy = 0; dy < 2; dy++)
                #pragma unroll
                for (int dx = 0; dx < 2; dx++) {
                    float lo, hi;
                    unpack2(acc[dy][dx][m], lo, hi);
                    m0 = fmaxf(m0, lo);
                    m1 = fmaxf(m1, hi);
                }
            g_g2[(2 * m + 0) * G2_AREA + py * G2_W + px] = m0 + b2[2 * m + 0];
            g_g2[(2 * m + 1) * G2_AREA + py * G2_W + px] = m1 + b2[2 * m + 1];
        }
    }
}

// ---------------------------------------------------------------------------
// Kernel C: gate conv3 (5x5 stride 5) + sigmoid. One warp per output:
// 25 lanes cover the 5x5 window, serial over 8 input channels, warp reduce.
// ---------------------------------------------------------------------------
__global__ __launch_bounds__(256)
void gate3_kernel(const float* __restrict__ w3,
                  const float* __restrict__ b3,
                  float* __restrict__ out_cv)
{
    __shared__ float s_w[200];
    int tid = threadIdx.x;
    if (tid < 200) s_w[tid] = w3[tid];
    __syncthreads();

    int lane = tid & 31;
    int o = blockIdx.x * 8 + (tid >> 5);
    if (o >= L_BLOCKS) return;
    int by = o / NW;
    int bx = o % NW;

    float v = 0.0f;
    if (lane < 25) {
        int ky = lane / 5, kx = lane % 5;
        const float* gp = &g_g2[(by * 5 + ky) * G2_W + (bx * 5 + kx)];
        #pragma unroll
        for (int ic = 0; ic < 8; ic++)
            v = fmaf(gp[ic * G2_AREA], s_w[ic * 25 + lane], v);
    }

    v += __shfl_xor_sync(0xffffffffu, v, 16);
    v += __shfl_xor_sync(0xffffffffu, v, 8);
    v += __shfl_xor_sync(0xffffffffu, v, 4);
    v += __shfl_xor_sync(0xffffffffu, v, 2);
    v += __shfl_xor_sync(0xffffffffu, v, 1);

    if (lane == 0)
        out_cv[o] = 1.0f / (1.0f + expf(-(v + b3[0])));
}

// ---------------------------------------------------------------------------
// Launch (light placed at position 3 mod 4 so the ncu window captures it)
// ---------------------------------------------------------------------------
extern "C" void kernel_launch(void* const* d_in, const int* in_sizes, int n_in,
                              void* d_out, int out_size)
{
    const float* in = (const float*)d_in[0];
    const float* w1 = (const float*)d_in[1];
    const float* b1 = (const float*)d_in[2];
    const float* w2 = (const float*)d_in[3];
    const float* b2 = (const float*)d_in[4];
    const float* w3 = (const float*)d_in[5];
    const float* b3 = (const float*)d_in[6];
    const float* wl = (const float*)d_in[7];
    const float* bl = (const float*)d_in[8];
    // complex expert weights (d_in[9..14]) are provably dead: sigmoid(x) > 1 never

    float* out = (float*)d_out;

    dim3 bt(256);
    gate1_kernel<<<dim3((G1_W + 15) / 16, (G1_H + 15) / 16), bt>>>(in, w1, b1);
    gate2_kernel<<<dim3((G2_W + 15) / 16, (G2_H + 15) / 16), bt>>>(w2, b2);
    gate3_kernel<<<L_BLOCKS / 8, 256>>>(w3, b3, out + OUT_IMG);
    light_kernel<<<L_BLOCKS, 256>>>(in, wl, bl, out);
}